// round 13
// baseline (speedup 1.0000x reference)
#include <cuda_runtime.h>
#include <math.h>
#include <stdint.h>

#define T_LEN 512
#define BATCH 64
#define ISZ   256
#define HID   512
#define GH    2048   // 4*HID, gate order f,i,o,c
#define NCTA  128

// ---------------- device scratch (no allocations allowed) ----------------
__device__ float g_gx[(size_t)T_LEN * GH * BATCH];  // [t][n=g*512+h][b] (bx+bh folded in)
__device__ float g_xT[(size_t)T_LEN * ISZ * BATCH]; // [t][k][b] transposed x
__device__ float g_h[2][HID * BATCH];               // double-buffered h, [h][b]
__device__ unsigned g_bars[4];                      // per-group arrival counters
__device__ volatile unsigned g_epochs[4];           // per-group release epochs
__device__ unsigned g_pro;                          // prologue barrier counter
__device__ volatile unsigned g_pro_done;            // prologue release

// ---------------- packed f32x2 helpers (sm_100+) ----------------
union F2U { float2 f; unsigned long long u; };
__device__ __forceinline__ float2 ffma2(float2 a, float2 b, float2 c) {
    F2U A, B, C, D; A.f = a; B.f = b; C.f = c;
    asm("fma.rn.f32x2 %0, %1, %2, %3;" : "=l"(D.u) : "l"(A.u), "l"(B.u), "l"(C.u));
    return D.f;
}
__device__ __forceinline__ float2 fadd2(float2 a, float2 b) {
    F2U A, B, D; A.f = a; B.f = b;
    asm("add.rn.f32x2 %0, %1, %2;" : "=l"(D.u) : "l"(A.u), "l"(B.u));
    return D.f;
}
__device__ __forceinline__ float fast_sigmoid(float x) {
    return __fdividef(1.0f, 1.0f + __expf(-x));
}
__device__ __forceinline__ float fast_tanh(float x) {
    return __fdividef(2.0f, 1.0f + __expf(-2.0f * x)) - 1.0f;
}

// ---------------- mbarrier helpers ----------------
__device__ __forceinline__ unsigned smem_u32(const void* p) {
    return (unsigned)__cvta_generic_to_shared(p);
}
__device__ __forceinline__ void mbar_init(unsigned bar, unsigned count) {
    asm volatile("mbarrier.init.shared.b64 [%0], %1;" :: "r"(bar), "r"(count) : "memory");
}
__device__ __forceinline__ void mbar_expect_tx(unsigned bar, unsigned bytes) {
    asm volatile("mbarrier.arrive.expect_tx.shared.b64 _, [%0], %1;"
                 :: "r"(bar), "r"(bytes) : "memory");
}
__device__ __forceinline__ void bulk_g2s(unsigned dst, const void* src, unsigned bytes, unsigned bar) {
    asm volatile("cp.async.bulk.shared::cta.global.mbarrier::complete_tx::bytes [%0], [%1], %2, [%3];"
                 :: "r"(dst), "l"(src), "r"(bytes), "r"(bar) : "memory");
}
__device__ __forceinline__ void mbar_wait(unsigned bar, unsigned parity) {
    asm volatile(
        "{\n\t"
        ".reg .pred P;\n\t"
        "WAIT_%=:\n\t"
        "mbarrier.try_wait.parity.acquire.cta.shared::cta.b64 P, [%0], %1;\n\t"
        "@!P bra WAIT_%=;\n\t"
        "}"
        :: "r"(bar), "r"(parity) : "memory");
}

// ---------------- init: zero h buffers + barrier state each replay ----------------
__global__ void init_state_kernel() {
    int idx = blockIdx.x * blockDim.x + threadIdx.x;
    if (idx < 2 * HID * BATCH) ((float*)g_h)[idx] = 0.0f;
    if (idx < 4) { g_bars[idx] = 0; g_epochs[idx] = 0; }
    if (idx == 4) { g_pro = 0; g_pro_done = 0; }
}

// ---------------- xT: x[t][b][i] -> g_xT[t][i][b] ----------------
__global__ __launch_bounds__(256) void xT_kernel(const float* __restrict__ x) {
    __shared__ float tile[256 * 65];
    const int tid = threadIdx.x;
    const int t   = blockIdx.x;
    const float* xt = x + (size_t)t * BATCH * ISZ;
    #pragma unroll 4
    for (int it = 0; it < 64; it++) {
        int idx = it * 256 + tid;
        int b = idx >> 8;            // 0..63
        int i = idx & 255;
        tile[i * 65 + b] = xt[idx];
    }
    __syncthreads();
    float* dst = g_xT + (size_t)t * ISZ * BATCH;
    #pragma unroll 4
    for (int it = 0; it < 64; it++) {
        int idx = it * 256 + tid;
        int i = idx >> 6;            // 0..255
        int b = idx & 63;
        dst[i * 64 + b] = tile[i * 65 + b];
    }
}

// ---------------- persistent kernel: recurrence + pipelined gx ----------------
// R8 structure (atomic+epoch sync, per-quarter TMA staging) unchanged.
// NEW: gx is produced inside the loop. CTA owns gx rows [bid*16, bid*16+16).
// Warp w computes row bid*16+w of gx(t+2) between TMA-issue and mbar_wait
// (overlaps the sync/staging window). gx(0..1) computed in a prologue
// followed by a one-time grid barrier. Safety: consumer prefetching gx(t) at
// step t has passed step t-1's epoch waits => all CTAs completed step t-2 =>
// gx(t) (written during step t-2, fenced before release) is complete.
__global__ __launch_bounds__(512, 1) void lstm_persistent(
        const float* __restrict__ Wh,
        const float* __restrict__ Wx,
        const float* __restrict__ bx,
        const float* __restrict__ bh,
        float* __restrict__ h_seq,
        float* __restrict__ out_hlast,
        float* __restrict__ out_clast) {
    extern __shared__ float sm[];
    float*  Wsp  = sm;                      // [512 k][16 r(hl,g)]  32 KB
    float*  hs   = sm + 8192;               // [512 k][64 b]       128 KB
    float2* red  = (float2*)(sm + 8192 + 32768);  // [8 ke][4 hl][2 gp][64 b] 32 KB
    float*  Wxs  = sm + 8192 + 32768 + 8192;      // [16 r][256 k]   16 KB
    unsigned long long* mbar = (unsigned long long*)(Wxs + 16 * 256);

    const int tid  = threadIdx.x;
    const int lane = tid & 31;
    const int warp = tid >> 5;
    const int bp   = lane;
    const int hlh  = warp & 1;
    const int ke   = warp >> 1;              // k-eighth 0..7
    const int khq  = ke >> 1;                // k-quarter 0..3 (mbar index)
    const int bid  = blockIdx.x;
    const int h0   = bid * 4;
    const int gid  = bid >> 5;               // this CTA's producer group
    const bool is_stager = ((warp % 5) == 0);    // warps 0,5,10,15
    const int  sq = warp / 5;                    // staged quarter

    // ---- stage Wsp once: Wsp[k*16 + hl*4 + g] = Wh[g*512 + h0 + hl][k]
    #pragma unroll
    for (int it = 0; it < 16; it++) {
        int idx = it * 512 + tid;            // 0..8191 = r*512 + k
        int r = idx >> 9, k = idx & 511;
        int hl = r >> 2, g = r & 3;
        Wsp[k * 16 + hl * 4 + g] = Wh[((size_t)(g * HID + h0 + hl)) * HID + k];
    }
    // ---- stage Wxs once: rows bid*16 .. bid*16+15 of Wx, row-major
    #pragma unroll
    for (int it = 0; it < 8; it++) {
        int idx = it * 512 + tid;            // 0..4095 = r*256 + k
        Wxs[idx] = Wx[(size_t)(bid * 16) * ISZ + idx];
    }
    if (tid == 0) {
        #pragma unroll
        for (int q = 0; q < 4; q++) mbar_init(smem_u32(&mbar[q]), 1);
    }

    // ---- per-warp gx context: row = bid*16 + warp, thread = batch pair
    const int gx_n = bid * 16 + warp;        // global gate-row
    const float gx_bias = __ldg(&bx[gx_n]) + __ldg(&bh[gx_n]);
    const float4* gx_w4 = (const float4*)(Wxs + warp * 256);

    // epilogue threads: tid < 128 -> cell (ehl = tid>>5, ebp = tid&31)
    const bool epi = (tid < 128);
    const int ehl = tid >> 5;
    const int ebp = tid & 31;
    const int eh  = h0 + ehl;
    float c0 = 0.0f, c1 = 0.0f;

    const unsigned my_bar  = smem_u32(&mbar[khq]);
    const unsigned hs_dst0 = smem_u32(hs);

    __syncthreads();

    // ---- prologue: gx(0) and gx(1), then one-time grid barrier
    #pragma unroll
    for (int tt = 0; tt < 2; tt++) {
        const float* xTp = g_xT + (size_t)tt * ISZ * BATCH + 2 * bp;
        float2 acc = make_float2(0.f, 0.f);
        #pragma unroll 4
        for (int k4 = 0; k4 < 64; k4++) {
            const float4 w4 = gx_w4[k4];
            const float2 x0 = __ldg((const float2*)(xTp + (k4 * 4 + 0) * 64));
            const float2 x1 = __ldg((const float2*)(xTp + (k4 * 4 + 1) * 64));
            const float2 x2 = __ldg((const float2*)(xTp + (k4 * 4 + 2) * 64));
            const float2 x3 = __ldg((const float2*)(xTp + (k4 * 4 + 3) * 64));
            acc = ffma2(x0, make_float2(w4.x, w4.x), acc);
            acc = ffma2(x1, make_float2(w4.y, w4.y), acc);
            acc = ffma2(x2, make_float2(w4.z, w4.z), acc);
            acc = ffma2(x3, make_float2(w4.w, w4.w), acc);
        }
        *(float2*)&g_gx[((size_t)tt * GH + gx_n) * BATCH + 2 * bp] =
            make_float2(acc.x + gx_bias, acc.y + gx_bias);
    }
    __syncthreads();
    if (tid == 0) {
        __threadfence();
        unsigned old = atomicAdd(&g_pro, 1u);
        if (old == NCTA - 1) g_pro_done = 1u;
        else while (g_pro_done == 0u) { __nanosleep(64); }
    }
    __syncthreads();

    int cur = 0;
    for (int t = 0; t < T_LEN; t++) {
        // ---- gx(t) prefetch for epilogue (safe: see header comment)
        float2 gxf, gxi, gxo, gxc;
        if (epi) {
            const float* gp = g_gx + ((size_t)t * GH + eh) * BATCH + 2 * ebp;
            gxf = __ldg((const float2*)(gp + (size_t)0 * HID * BATCH));
            gxi = __ldg((const float2*)(gp + (size_t)1 * HID * BATCH));
            gxo = __ldg((const float2*)(gp + (size_t)2 * HID * BATCH));
            gxc = __ldg((const float2*)(gp + (size_t)3 * HID * BATCH));
        }

        // ---- per-quarter stager: wait for its producer group, then copy 32 KB
        if (is_stager && lane == 0) {
            if (t > 0) {
                while (g_epochs[sq] < (unsigned)t) { __nanosleep(32); }
            }
            mbar_expect_tx(smem_u32(&mbar[sq]), 32768u);
            bulk_g2s(hs_dst0 + (unsigned)sq * 32768u,
                     (const char*)g_h[cur] + (unsigned)sq * 32768u,
                     32768u, smem_u32(&mbar[sq]));
        }

        // ---- pipelined gx(t+2): one row per warp, overlaps staging window
        if (t + 2 < T_LEN) {
            const int tt = t + 2;
            const float* xTp = g_xT + (size_t)tt * ISZ * BATCH + 2 * bp;
            float2 acc = make_float2(0.f, 0.f);
            #pragma unroll 4
            for (int k4 = 0; k4 < 64; k4++) {
                const float4 w4 = gx_w4[k4];
                const float2 x0 = __ldg((const float2*)(xTp + (k4 * 4 + 0) * 64));
                const float2 x1 = __ldg((const float2*)(xTp + (k4 * 4 + 1) * 64));
                const float2 x2 = __ldg((const float2*)(xTp + (k4 * 4 + 2) * 64));
                const float2 x3 = __ldg((const float2*)(xTp + (k4 * 4 + 3) * 64));
                acc = ffma2(x0, make_float2(w4.x, w4.x), acc);
                acc = ffma2(x1, make_float2(w4.y, w4.y), acc);
                acc = ffma2(x2, make_float2(w4.z, w4.z), acc);
                acc = ffma2(x3, make_float2(w4.w, w4.w), acc);
            }
            *(float2*)&g_gx[((size_t)tt * GH + gx_n) * BATCH + 2 * bp] =
                make_float2(acc.x + gx_bias, acc.y + gx_bias);
        }

        // ---- wait only for this warp's k-quarter
        mbar_wait(my_bar, (unsigned)(t & 1));

        // ---- compute: 64 k x (2 hl rows x 2 gate-pairs x 2 batches)
        float2 A000 = make_float2(0.f, 0.f), A001 = A000, A010 = A000, A011 = A000;
        float2 A100 = A000, A101 = A000, A110 = A000, A111 = A000;

        const float* wP = Wsp + (ke * 64) * 16 + 8 * hlh;
        const float* hP = hs + (ke * 64) * 64 + 2 * bp;

        #pragma unroll 8
        for (int kl = 0; kl < 64; kl++) {
            const float4 w4a = *(const float4*)(wP);       // rows: hl=2hlh, gates 0..3
            const float4 w4b = *(const float4*)(wP + 4);   // rows: hl=2hlh+1
            const float2 hv  = *(const float2*)(hP);
            const float2 d0 = make_float2(hv.x, hv.x);
            const float2 d1 = make_float2(hv.y, hv.y);
            const float2 w01a = make_float2(w4a.x, w4a.y);
            const float2 w23a = make_float2(w4a.z, w4a.w);
            const float2 w01b = make_float2(w4b.x, w4b.y);
            const float2 w23b = make_float2(w4b.z, w4b.w);
            A000 = ffma2(w01a, d0, A000);
            A001 = ffma2(w01a, d1, A001);
            A010 = ffma2(w23a, d0, A010);
            A011 = ffma2(w23a, d1, A011);
            A100 = ffma2(w01b, d0, A100);
            A101 = ffma2(w01b, d1, A101);
            A110 = ffma2(w23b, d0, A110);
            A111 = ffma2(w23b, d1, A111);
            wP += 16;
            hP += 64;
        }

        // ---- guard: previous step's red consumers must be done (skip at t=0)
        if (t > 0 && !epi) {
            asm volatile("bar.sync 2, 512;" ::: "memory");
        }

        // ---- scatter partials: red[((ke*4+hl)*2+gp)*64 + b] (f2 = gate pair)
        {
            const int hlA = 2 * hlh, hlB = 2 * hlh + 1;
            float4* r0 = (float4*)(red + ((ke * 4 + hlA) * 2 + 0) * 64 + 2 * bp);
            float4* r1 = (float4*)(red + ((ke * 4 + hlA) * 2 + 1) * 64 + 2 * bp);
            float4* r2 = (float4*)(red + ((ke * 4 + hlB) * 2 + 0) * 64 + 2 * bp);
            float4* r3 = (float4*)(red + ((ke * 4 + hlB) * 2 + 1) * 64 + 2 * bp);
            *r0 = make_float4(A000.x, A000.y, A001.x, A001.y);
            *r1 = make_float4(A010.x, A010.y, A011.x, A011.y);
            *r2 = make_float4(A100.x, A100.y, A101.x, A101.y);
            *r3 = make_float4(A110.x, A110.y, A111.x, A111.y);
        }
        __syncthreads();

        // ---- reduce 8 k-eighths + gates + publish (epi threads only)
        if (epi) {
            float2 s01_0 = make_float2(0.f, 0.f), s01_1 = s01_0;
            float2 s23_0 = s01_0, s23_1 = s01_0;
            #pragma unroll
            for (int q = 0; q < 8; q++) {
                const float4 v01 = *(const float4*)(red + ((q * 4 + ehl) * 2 + 0) * 64 + 2 * ebp);
                const float4 v23 = *(const float4*)(red + ((q * 4 + ehl) * 2 + 1) * 64 + 2 * ebp);
                s01_0 = fadd2(s01_0, make_float2(v01.x, v01.y));
                s01_1 = fadd2(s01_1, make_float2(v01.z, v01.w));
                s23_0 = fadd2(s23_0, make_float2(v23.x, v23.y));
                s23_1 = fadd2(s23_1, make_float2(v23.z, v23.w));
            }
            // s01 = (f, i), s23 = (o, c); gx already contains bx + bh
            const float pf0 = s01_0.x + gxf.x, pf1 = s01_1.x + gxf.y;
            const float pi0 = s01_0.y + gxi.x, pi1 = s01_1.y + gxi.y;
            const float po0 = s23_0.x + gxo.x, po1 = s23_1.x + gxo.y;
            const float pc0 = s23_0.y + gxc.x, pc1 = s23_1.y + gxc.y;

            const float f0 = fast_sigmoid(pf0), f1 = fast_sigmoid(pf1);
            const float i0 = fast_sigmoid(pi0), i1 = fast_sigmoid(pi1);
            const float o0 = fast_sigmoid(po0), o1 = fast_sigmoid(po1);
            const float q0 = fast_tanh(pc0),    q1 = fast_tanh(pc1);

            c0 = f0 * c0 + i0 * q0;
            c1 = f1 * c1 + i1 * q1;
            const float hn0 = o0 * fast_tanh(c0);
            const float hn1 = o1 * fast_tanh(c1);

            // publish next-step h first (only thing other CTAs wait on)
            __stcg((float2*)(g_h[cur ^ 1] + eh * BATCH + 2 * ebp),
                   make_float2(hn0, hn1));

            // red fully consumed -> release barrier 2
            asm volatile("bar.arrive 2, 512;" ::: "memory");

            // epi-only named barrier, then release (fence also covers gx(t+2)
            // stores of warps 0-3; warps 4-15's gx stores for step t complete
            // before their step-t scatter, hence before __syncthreads above)
            asm volatile("bar.sync 1, 128;" ::: "memory");
            if (tid == 0) {
                __threadfence();
                unsigned old = atomicAdd(&g_bars[gid], 1u);
                if (old == (unsigned)t * 32u + 31u) {
                    g_epochs[gid] = (unsigned)(t + 1);
                }
            }

            // off-critical-path outputs
            float* so = h_seq + ((size_t)t * BATCH + 2 * ebp) * HID + eh;
            so[0]   = hn0;
            so[HID] = hn1;
            if (t == T_LEN - 1) {
                out_hlast[(size_t)(2 * ebp) * HID + eh]     = hn0;
                out_hlast[(size_t)(2 * ebp + 1) * HID + eh] = hn1;
                out_clast[(size_t)(2 * ebp) * HID + eh]     = c0;
                out_clast[(size_t)(2 * ebp + 1) * HID + eh] = c1;
            }
        }

        cur ^= 1;
    }
}

// ---------------- launch ----------------
extern "C" void kernel_launch(void* const* d_in, const int* in_sizes, int n_in,
                              void* d_out, int out_size) {
    const float* x  = (const float*)d_in[0];
    const float* Wx = (const float*)d_in[1];
    const float* bx = (const float*)d_in[2];
    const float* Wh = (const float*)d_in[3];
    const float* bh = (const float*)d_in[4];

    float* out       = (float*)d_out;
    float* out_hlast = out + (size_t)T_LEN * BATCH * HID;
    float* out_clast = out_hlast + (size_t)BATCH * HID;

    const int ps_smem = (8192 + 32768 + 8192 + 4096) * sizeof(float) + 64; // 213056 B
    cudaFuncSetAttribute(lstm_persistent, cudaFuncAttributeMaxDynamicSharedMemorySize, ps_smem);

    init_state_kernel<<<128, 512>>>();
    xT_kernel<<<512, 256>>>(x);
    lstm_persistent<<<NCTA, 512, ps_smem>>>(Wh, Wx, bx, bh, out, out_hlast, out_clast);
}

// round 14
// speedup vs baseline: 1.6835x; 1.6835x over previous
#include <cuda_runtime.h>
#include <math.h>
#include <stdint.h>

#define T_LEN 512
#define BATCH 64
#define ISZ   256
#define HID   512
#define GH    2048   // 4*HID, gate order f,i,o,c
#define NCTA  128

// ---------------- device scratch (no allocations allowed) ----------------
__device__ float g_gx[(size_t)T_LEN * GH * BATCH];  // [t][n=g*512+h][b] (bx+bh folded in)
__device__ float g_h[2][HID * BATCH];               // double-buffered h, [h][b]
__device__ unsigned g_bars[4];                      // per-group arrival counters

// ---------------- packed f32x2 helpers (sm_100+) ----------------
union F2U { float2 f; unsigned long long u; };
__device__ __forceinline__ float2 ffma2(float2 a, float2 b, float2 c) {
    F2U A, B, C, D; A.f = a; B.f = b; C.f = c;
    asm("fma.rn.f32x2 %0, %1, %2, %3;" : "=l"(D.u) : "l"(A.u), "l"(B.u), "l"(C.u));
    return D.f;
}
__device__ __forceinline__ float2 fadd2(float2 a, float2 b) {
    F2U A, B, D; A.f = a; B.f = b;
    asm("add.rn.f32x2 %0, %1, %2;" : "=l"(D.u) : "l"(A.u), "l"(B.u));
    return D.f;
}
__device__ __forceinline__ float fast_sigmoid(float x) {
    return __fdividef(1.0f, 1.0f + __expf(-x));
}
__device__ __forceinline__ float fast_tanh(float x) {
    return __fdividef(2.0f, 1.0f + __expf(-2.0f * x)) - 1.0f;
}

// ---------------- release atomic + acquire poll ----------------
__device__ __forceinline__ void atom_add_release(unsigned* p, unsigned v) {
    unsigned old;
    asm volatile("atom.release.gpu.global.add.u32 %0, [%1], %2;"
                 : "=r"(old) : "l"(p), "r"(v) : "memory");
}
__device__ __forceinline__ unsigned ld_acquire(const unsigned* p) {
    unsigned v;
    asm volatile("ld.acquire.gpu.global.u32 %0, [%1];" : "=r"(v) : "l"(p) : "memory");
    return v;
}

// ---------------- mbarrier helpers ----------------
__device__ __forceinline__ unsigned smem_u32(const void* p) {
    return (unsigned)__cvta_generic_to_shared(p);
}
__device__ __forceinline__ void mbar_init(unsigned bar, unsigned count) {
    asm volatile("mbarrier.init.shared.b64 [%0], %1;" :: "r"(bar), "r"(count) : "memory");
}
__device__ __forceinline__ void mbar_expect_tx(unsigned bar, unsigned bytes) {
    asm volatile("mbarrier.arrive.expect_tx.shared.b64 _, [%0], %1;"
                 :: "r"(bar), "r"(bytes) : "memory");
}
__device__ __forceinline__ void bulk_g2s(unsigned dst, const void* src, unsigned bytes, unsigned bar) {
    asm volatile("cp.async.bulk.shared::cta.global.mbarrier::complete_tx::bytes [%0], [%1], %2, [%3];"
                 :: "r"(dst), "l"(src), "r"(bytes), "r"(bar) : "memory");
}
__device__ __forceinline__ void mbar_wait(unsigned bar, unsigned parity) {
    asm volatile(
        "{\n\t"
        ".reg .pred P;\n\t"
        "WAIT_%=:\n\t"
        "mbarrier.try_wait.parity.acquire.cta.shared::cta.b64 P, [%0], %1;\n\t"
        "@!P bra WAIT_%=;\n\t"
        "}"
        :: "r"(bar), "r"(parity) : "memory");
}

// ---------------- init: zero h buffers + barrier state ----------------
__global__ void init_state_kernel() {
    int idx = blockIdx.x * blockDim.x + threadIdx.x;
    if (idx < 2 * HID * BATCH) ((float*)g_h)[idx] = 0.0f;
    if (idx < 4) g_bars[idx] = 0;
}

// ---------------- gx = x @ Wx^T + (bx + bh)  -> g_gx[t][n][b] ----------------
// (R5/R8 original: coalesced stores, proven fastest variant)
__global__ __launch_bounds__(256) void gx_kernel(const float* __restrict__ x,
                                                 const float* __restrict__ Wx,
                                                 const float* __restrict__ bx,
                                                 const float* __restrict__ bh) {
    extern __shared__ float sm[];
    float* x_s = sm;               // [256][65] padded transpose
    float* Ws  = sm + 256 * 65;    // [32][256]
    const int tid = threadIdx.x;
    const int t   = blockIdx.y;
    const int n0  = blockIdx.x * 32;

    const float* xt = x + (size_t)t * BATCH * ISZ;
    #pragma unroll 4
    for (int r = 0; r < 64; r++) {
        int idx = r * 256 + tid;
        int b = idx >> 8;
        int i = idx & 255;
        x_s[i * 65 + b] = xt[idx];
    }
    const float* Wrow = Wx + (size_t)n0 * ISZ;
    #pragma unroll 4
    for (int r = 0; r < 32; r++) {
        int idx = r * 256 + tid;
        Ws[idx] = Wrow[idx];
    }
    __syncthreads();

    const int b  = tid & 63;
    const int ng = tid >> 6;
    float acc[8];
    #pragma unroll
    for (int j = 0; j < 8; j++) acc[j] = 0.0f;

    const float4* Ws4 = (const float4*)(Ws + (ng * 8) * ISZ);
    #pragma unroll 2
    for (int k4 = 0; k4 < 64; k4++) {
        const int k = k4 * 4;
        const float xa = x_s[(k + 0) * 65 + b];
        const float xb = x_s[(k + 1) * 65 + b];
        const float xc = x_s[(k + 2) * 65 + b];
        const float xd = x_s[(k + 3) * 65 + b];
        #pragma unroll
        for (int j = 0; j < 8; j++) {
            float4 w = Ws4[j * 64 + k4];
            acc[j] += w.x * xa;
            acc[j] += w.y * xb;
            acc[j] += w.z * xc;
            acc[j] += w.w * xd;
        }
    }

    const size_t base = ((size_t)t * GH + n0 + ng * 8) * BATCH + b;
    #pragma unroll
    for (int j = 0; j < 8; j++) {
        const int n = n0 + ng * 8 + j;
        g_gx[base + (size_t)j * BATCH] = acc[j] + __ldg(&bx[n]) + __ldg(&bh[n]);
    }
}

// ---------------- persistent recurrence kernel (R8 + fused-release sync) ----------------
// 128 CTAs (1/SM) x 512 threads (16 warps). CTA owns 4 hidden units (16 rows).
// h-quarter q produced by CTA group q (bid in [32q, 32q+32)) -> counter g_bars[q].
// Release = atom.release (fence fused); stagers poll the counter directly
// with ld.acquire (no separate epoch store hop).
// Warp w: ke = w>>1 (k-eighth, 64 k), hlh = w&1 (hl pair). Lane = batch pair.
// Stager warps 0/5/10/15 (one per SMSP) stage quarter w/5 via cp.async.bulk.
// red race guarded by named barrier 2 (epi arrives after consuming red).
__global__ __launch_bounds__(512, 1) void lstm_persistent(
        const float* __restrict__ Wh,
        float* __restrict__ h_seq,
        float* __restrict__ out_hlast,
        float* __restrict__ out_clast) {
    extern __shared__ float sm[];
    float*  Wsp  = sm;                      // [512 k][16 r(hl,g)]  32 KB
    float*  hs   = sm + 8192;               // [512 k][64 b]       128 KB
    float2* red  = (float2*)(sm + 8192 + 32768);  // [8 ke][4 hl][2 gp][64 b] 32 KB
    unsigned long long* mbar = (unsigned long long*)(sm + 8192 + 32768 + 8192);

    const int tid  = threadIdx.x;
    const int lane = tid & 31;
    const int warp = tid >> 5;
    const int bp   = lane;
    const int hlh  = warp & 1;
    const int ke   = warp >> 1;              // k-eighth 0..7
    const int khq  = ke >> 1;                // k-quarter 0..3 (mbar index)
    const int bid  = blockIdx.x;
    const int h0   = bid * 4;
    const int gid  = bid >> 5;               // this CTA's producer group
    const bool is_stager = ((warp % 5) == 0);    // warps 0,5,10,15
    const int  sq = warp / 5;                    // staged quarter

    // ---- stage Wsp once: Wsp[k*16 + hl*4 + g] = Wh[g*512 + h0 + hl][k]
    #pragma unroll
    for (int it = 0; it < 16; it++) {
        int idx = it * 512 + tid;            // 0..8191 = r*512 + k
        int r = idx >> 9, k = idx & 511;
        int hl = r >> 2, g = r & 3;
        Wsp[k * 16 + hl * 4 + g] = Wh[((size_t)(g * HID + h0 + hl)) * HID + k];
    }
    if (tid == 0) {
        #pragma unroll
        for (int q = 0; q < 4; q++) mbar_init(smem_u32(&mbar[q]), 1);
    }

    // epilogue threads: tid < 128 -> cell (ehl = tid>>5, ebp = tid&31)
    const bool epi = (tid < 128);
    const int ehl = tid >> 5;
    const int ebp = tid & 31;
    const int eh  = h0 + ehl;
    float c0 = 0.0f, c1 = 0.0f;

    const unsigned my_bar  = smem_u32(&mbar[khq]);
    const unsigned hs_dst0 = smem_u32(hs);

    __syncthreads();

    int cur = 0;
    for (int t = 0; t < T_LEN; t++) {
        // ---- gx prefetch (h-independent; overlaps the counter wait)
        float2 gxf, gxi, gxo, gxc;
        if (epi) {
            const float* gp = g_gx + ((size_t)t * GH + eh) * BATCH + 2 * ebp;
            gxf = __ldg((const float2*)(gp + (size_t)0 * HID * BATCH));
            gxi = __ldg((const float2*)(gp + (size_t)1 * HID * BATCH));
            gxo = __ldg((const float2*)(gp + (size_t)2 * HID * BATCH));
            gxc = __ldg((const float2*)(gp + (size_t)3 * HID * BATCH));
        }

        // ---- per-quarter stager: poll producer-group counter, then copy 32 KB
        if (is_stager && lane == 0) {
            if (t > 0) {
                const unsigned need = (unsigned)t * 32u;
                while (ld_acquire(&g_bars[sq]) < need) { __nanosleep(32); }
            }
            mbar_expect_tx(smem_u32(&mbar[sq]), 32768u);
            bulk_g2s(hs_dst0 + (unsigned)sq * 32768u,
                     (const char*)g_h[cur] + (unsigned)sq * 32768u,
                     32768u, smem_u32(&mbar[sq]));
        }

        // ---- wait only for this warp's k-quarter
        mbar_wait(my_bar, (unsigned)(t & 1));

        // ---- compute: 64 k x (2 hl rows x 2 gate-pairs x 2 batches)
        float2 A000 = make_float2(0.f, 0.f), A001 = A000, A010 = A000, A011 = A000;
        float2 A100 = A000, A101 = A000, A110 = A000, A111 = A000;

        const float* wP = Wsp + (ke * 64) * 16 + 8 * hlh;
        const float* hP = hs + (ke * 64) * 64 + 2 * bp;

        #pragma unroll 8
        for (int kl = 0; kl < 64; kl++) {
            const float4 w4a = *(const float4*)(wP);       // rows: hl=2hlh, gates 0..3
            const float4 w4b = *(const float4*)(wP + 4);   // rows: hl=2hlh+1
            const float2 hv  = *(const float2*)(hP);
            const float2 d0 = make_float2(hv.x, hv.x);
            const float2 d1 = make_float2(hv.y, hv.y);
            const float2 w01a = make_float2(w4a.x, w4a.y);
            const float2 w23a = make_float2(w4a.z, w4a.w);
            const float2 w01b = make_float2(w4b.x, w4b.y);
            const float2 w23b = make_float2(w4b.z, w4b.w);
            A000 = ffma2(w01a, d0, A000);
            A001 = ffma2(w01a, d1, A001);
            A010 = ffma2(w23a, d0, A010);
            A011 = ffma2(w23a, d1, A011);
            A100 = ffma2(w01b, d0, A100);
            A101 = ffma2(w01b, d1, A101);
            A110 = ffma2(w23b, d0, A110);
            A111 = ffma2(w23b, d1, A111);
            wP += 16;
            hP += 64;
        }

        // ---- guard: previous step's red consumers must be done (skip at t=0)
        if (t > 0 && !epi) {
            asm volatile("bar.sync 2, 512;" ::: "memory");
        }

        // ---- scatter partials: red[((ke*4+hl)*2+gp)*64 + b] (f2 = gate pair)
        {
            const int hlA = 2 * hlh, hlB = 2 * hlh + 1;
            float4* r0 = (float4*)(red + ((ke * 4 + hlA) * 2 + 0) * 64 + 2 * bp);
            float4* r1 = (float4*)(red + ((ke * 4 + hlA) * 2 + 1) * 64 + 2 * bp);
            float4* r2 = (float4*)(red + ((ke * 4 + hlB) * 2 + 0) * 64 + 2 * bp);
            float4* r3 = (float4*)(red + ((ke * 4 + hlB) * 2 + 1) * 64 + 2 * bp);
            *r0 = make_float4(A000.x, A000.y, A001.x, A001.y);
            *r1 = make_float4(A010.x, A010.y, A011.x, A011.y);
            *r2 = make_float4(A100.x, A100.y, A101.x, A101.y);
            *r3 = make_float4(A110.x, A110.y, A111.x, A111.y);
        }
        __syncthreads();

        // ---- reduce 8 k-eighths + gates + publish (epi threads only)
        if (epi) {
            float2 s01_0 = make_float2(0.f, 0.f), s01_1 = s01_0;
            float2 s23_0 = s01_0, s23_1 = s01_0;
            #pragma unroll
            for (int q = 0; q < 8; q++) {
                const float4 v01 = *(const float4*)(red + ((q * 4 + ehl) * 2 + 0) * 64 + 2 * ebp);
                const float4 v23 = *(const float4*)(red + ((q * 4 + ehl) * 2 + 1) * 64 + 2 * ebp);
                s01_0 = fadd2(s01_0, make_float2(v01.x, v01.y));
                s01_1 = fadd2(s01_1, make_float2(v01.z, v01.w));
                s23_0 = fadd2(s23_0, make_float2(v23.x, v23.y));
                s23_1 = fadd2(s23_1, make_float2(v23.z, v23.w));
            }
            // s01 = (f, i), s23 = (o, c); gx already contains bx + bh
            const float pf0 = s01_0.x + gxf.x, pf1 = s01_1.x + gxf.y;
            const float pi0 = s01_0.y + gxi.x, pi1 = s01_1.y + gxi.y;
            const float po0 = s23_0.x + gxo.x, po1 = s23_1.x + gxo.y;
            const float pc0 = s23_0.y + gxc.x, pc1 = s23_1.y + gxc.y;

            const float f0 = fast_sigmoid(pf0), f1 = fast_sigmoid(pf1);
            const float i0 = fast_sigmoid(pi0), i1 = fast_sigmoid(pi1);
            const float o0 = fast_sigmoid(po0), o1 = fast_sigmoid(po1);
            const float q0 = fast_tanh(pc0),    q1 = fast_tanh(pc1);

            c0 = f0 * c0 + i0 * q0;
            c1 = f1 * c1 + i1 * q1;
            const float hn0 = o0 * fast_tanh(c0);
            const float hn1 = o1 * fast_tanh(c1);

            // publish next-step h first (only thing other CTAs wait on)
            __stcg((float2*)(g_h[cur ^ 1] + eh * BATCH + 2 * ebp),
                   make_float2(hn0, hn1));

            // red fully consumed (values folded into hn/c) -> release barrier 2
            asm volatile("bar.arrive 2, 512;" ::: "memory");

            // epi-only named barrier (h stores ordered), then fused release-add
            asm volatile("bar.sync 1, 128;" ::: "memory");
            if (tid == 0) {
                atom_add_release(&g_bars[gid], 1u);
            }

            // off-critical-path outputs
            float* so = h_seq + ((size_t)t * BATCH + 2 * ebp) * HID + eh;
            so[0]   = hn0;
            so[HID] = hn1;
            if (t == T_LEN - 1) {
                out_hlast[(size_t)(2 * ebp) * HID + eh]     = hn0;
                out_hlast[(size_t)(2 * ebp + 1) * HID + eh] = hn1;
                out_clast[(size_t)(2 * ebp) * HID + eh]     = c0;
                out_clast[(size_t)(2 * ebp + 1) * HID + eh] = c1;
            }
        }

        cur ^= 1;
    }
}

// ---------------- launch ----------------
extern "C" void kernel_launch(void* const* d_in, const int* in_sizes, int n_in,
                              void* d_out, int out_size) {
    const float* x  = (const float*)d_in[0];
    const float* Wx = (const float*)d_in[1];
    const float* bx = (const float*)d_in[2];
    const float* Wh = (const float*)d_in[3];
    const float* bh = (const float*)d_in[4];

    float* out       = (float*)d_out;
    float* out_hlast = out + (size_t)T_LEN * BATCH * HID;
    float* out_clast = out_hlast + (size_t)BATCH * HID;

    const int gx_smem = (256 * 65 + 32 * 256) * sizeof(float);      // 99328 B
    const int ps_smem = (8192 + 32768 + 8192) * sizeof(float) + 64; // 196672 B
    cudaFuncSetAttribute(gx_kernel,       cudaFuncAttributeMaxDynamicSharedMemorySize, gx_smem);
    cudaFuncSetAttribute(lstm_persistent, cudaFuncAttributeMaxDynamicSharedMemorySize, ps_smem);

    init_state_kernel<<<128, 512>>>();
    gx_kernel<<<dim3(64, 512), 256, gx_smem>>>(x, Wx, bx, bh);
    lstm_persistent<<<NCTA, 512, ps_smem>>>(Wh, out, out_hlast, out_clast);
}

// round 16
// speedup vs baseline: 1.7194x; 1.0213x over previous
#include <cuda_runtime.h>
#include <cuda_fp16.h>
#include <math.h>
#include <stdint.h>

#define T_LEN 512
#define BATCH 64
#define ISZ   256
#define HID   512
#define GH    2048   // 4*HID, gate order f,i,o,c
#define NCTA  128

// ---------------- device scratch (no allocations allowed) ----------------
__device__ float g_gx[(size_t)T_LEN * GH * BATCH];  // [t][n=g*512+h][b] (bx+bh folded in)
__device__ __align__(16) __half g_h[2][HID * BATCH]; // double-buffered h (fp16 transport), [h][b]
__device__ unsigned g_bars[4];                      // per-group arrival counters
__device__ volatile unsigned g_epochs[4];           // per-group release epochs

// ---------------- packed f32x2 helpers (sm_100+) ----------------
union F2U { float2 f; unsigned long long u; };
__device__ __forceinline__ float2 ffma2(float2 a, float2 b, float2 c) {
    F2U A, B, C, D; A.f = a; B.f = b; C.f = c;
    asm("fma.rn.f32x2 %0, %1, %2, %3;" : "=l"(D.u) : "l"(A.u), "l"(B.u), "l"(C.u));
    return D.f;
}
__device__ __forceinline__ float2 fadd2(float2 a, float2 b) {
    F2U A, B, D; A.f = a; B.f = b;
    asm("add.rn.f32x2 %0, %1, %2;" : "=l"(D.u) : "l"(A.u), "l"(B.u));
    return D.f;
}
__device__ __forceinline__ float fast_sigmoid(float x) {
    return __fdividef(1.0f, 1.0f + __expf(-x));
}
__device__ __forceinline__ float fast_tanh(float x) {
    return __fdividef(2.0f, 1.0f + __expf(-2.0f * x)) - 1.0f;
}

// ---------------- mbarrier helpers ----------------
__device__ __forceinline__ unsigned smem_u32(const void* p) {
    return (unsigned)__cvta_generic_to_shared(p);
}
__device__ __forceinline__ void mbar_init(unsigned bar, unsigned count) {
    asm volatile("mbarrier.init.shared.b64 [%0], %1;" :: "r"(bar), "r"(count) : "memory");
}
__device__ __forceinline__ void mbar_expect_tx(unsigned bar, unsigned bytes) {
    asm volatile("mbarrier.arrive.expect_tx.shared.b64 _, [%0], %1;"
                 :: "r"(bar), "r"(bytes) : "memory");
}
__device__ __forceinline__ void bulk_g2s(unsigned dst, const void* src, unsigned bytes, unsigned bar) {
    asm volatile("cp.async.bulk.shared::cta.global.mbarrier::complete_tx::bytes [%0], [%1], %2, [%3];"
                 :: "r"(dst), "l"(src), "r"(bytes), "r"(bar) : "memory");
}
__device__ __forceinline__ void mbar_wait(unsigned bar, unsigned parity) {
    asm volatile(
        "{\n\t"
        ".reg .pred P;\n\t"
        "WAIT_%=:\n\t"
        "mbarrier.try_wait.parity.acquire.cta.shared::cta.b64 P, [%0], %1;\n\t"
        "@!P bra WAIT_%=;\n\t"
        "}"
        :: "r"(bar), "r"(parity) : "memory");
}

// ---------------- init: zero h buffers + barrier state ----------------
__global__ void init_state_kernel() {
    int idx = blockIdx.x * blockDim.x + threadIdx.x;
    if (idx < HID * BATCH) ((uint32_t*)g_h)[idx] = 0u;  // 32768 u32 = both fp16 buffers
    if (idx < 4) { g_bars[idx] = 0; g_epochs[idx] = 0; }
}

// ---------------- gx = x @ Wx^T + (bx + bh)  -> g_gx[t][n][b] ----------------
// (R5/R8 original: coalesced stores, proven fastest variant)
__global__ __launch_bounds__(256) void gx_kernel(const float* __restrict__ x,
                                                 const float* __restrict__ Wx,
                                                 const float* __restrict__ bx,
                                                 const float* __restrict__ bh) {
    extern __shared__ float sm[];
    float* x_s = sm;               // [256][65] padded transpose
    float* Ws  = sm + 256 * 65;    // [32][256]
    const int tid = threadIdx.x;
    const int t   = blockIdx.y;
    const int n0  = blockIdx.x * 32;

    const float* xt = x + (size_t)t * BATCH * ISZ;
    #pragma unroll 4
    for (int r = 0; r < 64; r++) {
        int idx = r * 256 + tid;
        int b = idx >> 8;
        int i = idx & 255;
        x_s[i * 65 + b] = xt[idx];
    }
    const float* Wrow = Wx + (size_t)n0 * ISZ;
    #pragma unroll 4
    for (int r = 0; r < 32; r++) {
        int idx = r * 256 + tid;
        Ws[idx] = Wrow[idx];
    }
    __syncthreads();

    const int b  = tid & 63;
    const int ng = tid >> 6;
    float acc[8];
    #pragma unroll
    for (int j = 0; j < 8; j++) acc[j] = 0.0f;

    const float4* Ws4 = (const float4*)(Ws + (ng * 8) * ISZ);
    #pragma unroll 2
    for (int k4 = 0; k4 < 64; k4++) {
        const int k = k4 * 4;
        const float xa = x_s[(k + 0) * 65 + b];
        const float xb = x_s[(k + 1) * 65 + b];
        const float xc = x_s[(k + 2) * 65 + b];
        const float xd = x_s[(k + 3) * 65 + b];
        #pragma unroll
        for (int j = 0; j < 8; j++) {
            float4 w = Ws4[j * 64 + k4];
            acc[j] += w.x * xa;
            acc[j] += w.y * xb;
            acc[j] += w.z * xc;
            acc[j] += w.w * xd;
        }
    }

    const size_t base = ((size_t)t * GH + n0 + ng * 8) * BATCH + b;
    #pragma unroll
    for (int j = 0; j < 8; j++) {
        const int n = n0 + ng * 8 + j;
        g_gx[base + (size_t)j * BATCH] = acc[j] + __ldg(&bx[n]) + __ldg(&bh[n]);
    }
}

// ---------------- persistent recurrence kernel (R8 + fp16 h transport) ----------------
// 128 CTAs (1/SM) x 512 threads (16 warps). CTA owns 4 hidden units (16 rows).
// h-quarter q produced by CTA group q (bid in [32q, 32q+32)) -> g_epochs[q].
// h transported as fp16 ([h][b] half): staging traffic halves (16 KB/quarter),
// math stays fp32 (convert on load), h_seq/out_* written fp32 from registers.
// SMEM layout (float offsets): Wsp [0,8192), hs fp16 [8192,24576) = 64 KB,
// red [24576,32768), mbar after. (R14's NaN was red overlapping hs.)
// Warp w: ke = w>>1 (k-eighth, 64 k), hlh = w&1 (hl pair). Lane = batch pair.
// Stager warps 0/5/10/15 (one per SMSP) stage quarter w/5 via cp.async.bulk.
// red race guarded by named barrier 2 (epi arrives after consuming red).
__global__ __launch_bounds__(512, 1) void lstm_persistent(
        const float* __restrict__ Wh,
        float* __restrict__ h_seq,
        float* __restrict__ out_hlast,
        float* __restrict__ out_clast) {
    extern __shared__ float sm[];
    float*  Wsp  = sm;                        // [512 k][16 r(hl,g)]  32 KB
    __half* hs   = (__half*)(sm + 8192);      // [512 k][64 b] fp16   64 KB
    float2* red  = (float2*)(sm + 24576);     // [8 ke][4 hl][2 gp][64 b] 32 KB
    unsigned long long* mbar = (unsigned long long*)(sm + 32768);

    const int tid  = threadIdx.x;
    const int lane = tid & 31;
    const int warp = tid >> 5;
    const int bp   = lane;
    const int hlh  = warp & 1;
    const int ke   = warp >> 1;              // k-eighth 0..7
    const int khq  = ke >> 1;                // k-quarter 0..3 (mbar index)
    const int bid  = blockIdx.x;
    const int h0   = bid * 4;
    const int gid  = bid >> 5;               // this CTA's producer group
    const bool is_stager = ((warp % 5) == 0);    // warps 0,5,10,15
    const int  sq = warp / 5;                    // staged quarter

    // ---- stage Wsp once: Wsp[k*16 + hl*4 + g] = Wh[g*512 + h0 + hl][k]
    #pragma unroll
    for (int it = 0; it < 16; it++) {
        int idx = it * 512 + tid;            // 0..8191 = r*512 + k
        int r = idx >> 9, k = idx & 511;
        int hl = r >> 2, g = r & 3;
        Wsp[k * 16 + hl * 4 + g] = Wh[((size_t)(g * HID + h0 + hl)) * HID + k];
    }
    if (tid == 0) {
        #pragma unroll
        for (int q = 0; q < 4; q++) mbar_init(smem_u32(&mbar[q]), 1);
    }

    // epilogue threads: tid < 128 -> cell (ehl = tid>>5, ebp = tid&31)
    const bool epi = (tid < 128);
    const int ehl = tid >> 5;
    const int ebp = tid & 31;
    const int eh  = h0 + ehl;
    float c0 = 0.0f, c1 = 0.0f;

    const unsigned my_bar  = smem_u32(&mbar[khq]);
    const unsigned hs_dst0 = smem_u32(hs);

    __syncthreads();

    int cur = 0;
    for (int t = 0; t < T_LEN; t++) {
        // ---- gx prefetch (h-independent; overlaps the epoch wait)
        float2 gxf, gxi, gxo, gxc;
        if (epi) {
            const float* gp = g_gx + ((size_t)t * GH + eh) * BATCH + 2 * ebp;
            gxf = __ldg((const float2*)(gp + (size_t)0 * HID * BATCH));
            gxi = __ldg((const float2*)(gp + (size_t)1 * HID * BATCH));
            gxo = __ldg((const float2*)(gp + (size_t)2 * HID * BATCH));
            gxc = __ldg((const float2*)(gp + (size_t)3 * HID * BATCH));
        }

        // ---- per-quarter stager: wait for its producer group, then copy 16 KB
        if (is_stager && lane == 0) {
            if (t > 0) {
                while (g_epochs[sq] < (unsigned)t) { __nanosleep(32); }
            }
            mbar_expect_tx(smem_u32(&mbar[sq]), 16384u);
            bulk_g2s(hs_dst0 + (unsigned)sq * 16384u,
                     (const char*)g_h[cur] + (unsigned)sq * 16384u,
                     16384u, smem_u32(&mbar[sq]));
        }

        // ---- wait only for this warp's k-quarter
        mbar_wait(my_bar, (unsigned)(t & 1));

        // ---- compute: 64 k x (2 hl rows x 2 gate-pairs x 2 batches)
        float2 A000 = make_float2(0.f, 0.f), A001 = A000, A010 = A000, A011 = A000;
        float2 A100 = A000, A101 = A000, A110 = A000, A111 = A000;

        const float*  wP = Wsp + (ke * 64) * 16 + 8 * hlh;
        const __half* hP = hs + (ke * 64) * 64 + 2 * bp;

        #pragma unroll 8
        for (int kl = 0; kl < 64; kl++) {
            const float4 w4a = *(const float4*)(wP);       // rows: hl=2hlh, gates 0..3
            const float4 w4b = *(const float4*)(wP + 4);   // rows: hl=2hlh+1
            const __half2 hh = *(const __half2*)(hP);
            const float2 hf  = __half22float2(hh);
            const float2 d0 = make_float2(hf.x, hf.x);
            const float2 d1 = make_float2(hf.y, hf.y);
            const float2 w01a = make_float2(w4a.x, w4a.y);
            const float2 w23a = make_float2(w4a.z, w4a.w);
            const float2 w01b = make_float2(w4b.x, w4b.y);
            const float2 w23b = make_float2(w4b.z, w4b.w);
            A000 = ffma2(w01a, d0, A000);
            A001 = ffma2(w01a, d1, A001);
            A010 = ffma2(w23a, d0, A010);
            A011 = ffma2(w23a, d1, A011);
            A100 = ffma2(w01b, d0, A100);
            A101 = ffma2(w01b, d1, A101);
            A110 = ffma2(w23b, d0, A110);
            A111 = ffma2(w23b, d1, A111);
            wP += 16;
            hP += 64;
        }

        // ---- guard: previous step's red consumers must be done (skip at t=0)
        if (t > 0 && !epi) {
            asm volatile("bar.sync 2, 512;" ::: "memory");
        }

        // ---- scatter partials: red[((ke*4+hl)*2+gp)*64 + b] (f2 = gate pair)
        {
            const int hlA = 2 * hlh, hlB = 2 * hlh + 1;
            float4* r0 = (float4*)(red + ((ke * 4 + hlA) * 2 + 0) * 64 + 2 * bp);
            float4* r1 = (float4*)(red + ((ke * 4 + hlA) * 2 + 1) * 64 + 2 * bp);
            float4* r2 = (float4*)(red + ((ke * 4 + hlB) * 2 + 0) * 64 + 2 * bp);
            float4* r3 = (float4*)(red + ((ke * 4 + hlB) * 2 + 1) * 64 + 2 * bp);
            *r0 = make_float4(A000.x, A000.y, A001.x, A001.y);
            *r1 = make_float4(A010.x, A010.y, A011.x, A011.y);
            *r2 = make_float4(A100.x, A100.y, A101.x, A101.y);
            *r3 = make_float4(A110.x, A110.y, A111.x, A111.y);
        }
        __syncthreads();

        // ---- reduce 8 k-eighths + gates + publish (epi threads only)
        if (epi) {
            float2 s01_0 = make_float2(0.f, 0.f), s01_1 = s01_0;
            float2 s23_0 = s01_0, s23_1 = s01_0;
            #pragma unroll
            for (int q = 0; q < 8; q++) {
                const float4 v01 = *(const float4*)(red + ((q * 4 + ehl) * 2 + 0) * 64 + 2 * ebp);
                const float4 v23 = *(const float4*)(red + ((q * 4 + ehl) * 2 + 1) * 64 + 2 * ebp);
                s01_0 = fadd2(s01_0, make_float2(v01.x, v01.y));
                s01_1 = fadd2(s01_1, make_float2(v01.z, v01.w));
                s23_0 = fadd2(s23_0, make_float2(v23.x, v23.y));
                s23_1 = fadd2(s23_1, make_float2(v23.z, v23.w));
            }
            // s01 = (f, i), s23 = (o, c); gx already contains bx + bh
            const float pf0 = s01_0.x + gxf.x, pf1 = s01_1.x + gxf.y;
            const float pi0 = s01_0.y + gxi.x, pi1 = s01_1.y + gxi.y;
            const float po0 = s23_0.x + gxo.x, po1 = s23_1.x + gxo.y;
            const float pc0 = s23_0.y + gxc.x, pc1 = s23_1.y + gxc.y;

            const float f0 = fast_sigmoid(pf0), f1 = fast_sigmoid(pf1);
            const float i0 = fast_sigmoid(pi0), i1 = fast_sigmoid(pi1);
            const float o0 = fast_sigmoid(po0), o1 = fast_sigmoid(po1);
            const float q0 = fast_tanh(pc0),    q1 = fast_tanh(pc1);

            c0 = f0 * c0 + i0 * q0;
            c1 = f1 * c1 + i1 * q1;
            const float hn0 = o0 * fast_tanh(c0);
            const float hn1 = o1 * fast_tanh(c1);

            // publish next-step h as fp16 (the only cross-CTA dependency)
            {
                __half2 h2 = __floats2half2_rn(hn0, hn1);
                __stcg((unsigned*)(g_h[cur ^ 1] + eh * BATCH + 2 * ebp),
                       *(unsigned*)&h2);
            }

            // red fully consumed (values folded into hn/c) -> release barrier 2
            asm volatile("bar.arrive 2, 512;" ::: "memory");

            // epi-only named barrier (warps 0-3, 128 threads), then release
            asm volatile("bar.sync 1, 128;" ::: "memory");
            if (tid == 0) {
                __threadfence();
                unsigned old = atomicAdd(&g_bars[gid], 1u);
                if (old == (unsigned)t * 32u + 31u) {
                    g_epochs[gid] = (unsigned)(t + 1);
                }
            }

            // off-critical-path outputs (full fp32 precision from registers)
            float* so = h_seq + ((size_t)t * BATCH + 2 * ebp) * HID + eh;
            so[0]   = hn0;
            so[HID] = hn1;
            if (t == T_LEN - 1) {
                out_hlast[(size_t)(2 * ebp) * HID + eh]     = hn0;
                out_hlast[(size_t)(2 * ebp + 1) * HID + eh] = hn1;
                out_clast[(size_t)(2 * ebp) * HID + eh]     = c0;
                out_clast[(size_t)(2 * ebp + 1) * HID + eh] = c1;
            }
        }

        cur ^= 1;
    }
}

// ---------------- launch ----------------
extern "C" void kernel_launch(void* const* d_in, const int* in_sizes, int n_in,
                              void* d_out, int out_size) {
    const float* x  = (const float*)d_in[0];
    const float* Wx = (const float*)d_in[1];
    const float* bx = (const float*)d_in[2];
    const float* Wh = (const float*)d_in[3];
    const float* bh = (const float*)d_in[4];

    float* out       = (float*)d_out;
    float* out_hlast = out + (size_t)T_LEN * BATCH * HID;
    float* out_clast = out_hlast + (size_t)BATCH * HID;

    const int gx_smem = (256 * 65 + 32 * 256) * sizeof(float);      // 99328 B
    const int ps_smem = (8192 + 16384 + 8192) * sizeof(float) + 64; // 131136 B
    cudaFuncSetAttribute(gx_kernel,       cudaFuncAttributeMaxDynamicSharedMemorySize, gx_smem);
    cudaFuncSetAttribute(lstm_persistent, cudaFuncAttributeMaxDynamicSharedMemorySize, ps_smem);

    init_state_kernel<<<128, 512>>>();
    gx_kernel<<<dim3(64, 512), 256, gx_smem>>>(x, Wx, bx, bh);
    lstm_persistent<<<NCTA, 512, ps_smem>>>(Wh, out, out_hlast, out_clast);
}

// round 17
// speedup vs baseline: 1.7933x; 1.0430x over previous
#include <cuda_runtime.h>
#include <cuda_fp16.h>
#include <math.h>
#include <stdint.h>

#define T_LEN 512
#define BATCH 64
#define ISZ   256
#define HID   512
#define GH    2048   // 4*HID, gate order f,i,o,c
#define NCTA  128

// ---------------- device scratch (no allocations allowed) ----------------
__device__ float g_gx[(size_t)T_LEN * GH * BATCH];  // [t][n=g*512+h][b] (bx+bh folded in)
__device__ __align__(16) __half g_h[2][HID * BATCH]; // double-buffered h (fp16 transport), [h][b]
__device__ unsigned g_bars[4];                      // per-group arrival counters
__device__ volatile unsigned g_epochs[4];           // per-group release epochs

// ---------------- packed f32x2 helpers (sm_100+) ----------------
union F2U { float2 f; unsigned long long u; };
__device__ __forceinline__ float2 ffma2(float2 a, float2 b, float2 c) {
    F2U A, B, C, D; A.f = a; B.f = b; C.f = c;
    asm("fma.rn.f32x2 %0, %1, %2, %3;" : "=l"(D.u) : "l"(A.u), "l"(B.u), "l"(C.u));
    return D.f;
}
__device__ __forceinline__ float2 fadd2(float2 a, float2 b) {
    F2U A, B, D; A.f = a; B.f = b;
    asm("add.rn.f32x2 %0, %1, %2;" : "=l"(D.u) : "l"(A.u), "l"(B.u));
    return D.f;
}
__device__ __forceinline__ float fast_sigmoid(float x) {
    return __fdividef(1.0f, 1.0f + __expf(-x));
}
__device__ __forceinline__ float fast_tanh(float x) {
    return __fdividef(2.0f, 1.0f + __expf(-2.0f * x)) - 1.0f;
}

// ---------------- mbarrier helpers ----------------
__device__ __forceinline__ unsigned smem_u32(const void* p) {
    return (unsigned)__cvta_generic_to_shared(p);
}
__device__ __forceinline__ void mbar_init(unsigned bar, unsigned count) {
    asm volatile("mbarrier.init.shared.b64 [%0], %1;" :: "r"(bar), "r"(count) : "memory");
}
__device__ __forceinline__ void mbar_expect_tx(unsigned bar, unsigned bytes) {
    asm volatile("mbarrier.arrive.expect_tx.shared.b64 _, [%0], %1;"
                 :: "r"(bar), "r"(bytes) : "memory");
}
__device__ __forceinline__ void bulk_g2s(unsigned dst, const void* src, unsigned bytes, unsigned bar) {
    asm volatile("cp.async.bulk.shared::cta.global.mbarrier::complete_tx::bytes [%0], [%1], %2, [%3];"
                 :: "r"(dst), "l"(src), "r"(bytes), "r"(bar) : "memory");
}
__device__ __forceinline__ void mbar_wait(unsigned bar, unsigned parity) {
    asm volatile(
        "{\n\t"
        ".reg .pred P;\n\t"
        "WAIT_%=:\n\t"
        "mbarrier.try_wait.parity.acquire.cta.shared::cta.b64 P, [%0], %1;\n\t"
        "@!P bra WAIT_%=;\n\t"
        "}"
        :: "r"(bar), "r"(parity) : "memory");
}

// ---------------- init: zero h buffers + barrier state ----------------
__global__ void init_state_kernel() {
    int idx = blockIdx.x * blockDim.x + threadIdx.x;
    if (idx < HID * BATCH) ((uint32_t*)g_h)[idx] = 0u;  // 32768 u32 = both fp16 buffers
    if (idx < 4) { g_bars[idx] = 0; g_epochs[idx] = 0; }
}

// ---------------- gx = x @ Wx^T + (bx + bh)  -> g_gx[t][n][b] ----------------
// R5/R8 memory behavior EXACTLY (same staging, same mapping, same coalesced
// stores); inner loop switched to k-paired FFMA2: accumulator = (even-k,
// odd-k) partial pair, weight pairs come free from the existing LDS.128.
__global__ __launch_bounds__(256) void gx_kernel(const float* __restrict__ x,
                                                 const float* __restrict__ Wx,
                                                 const float* __restrict__ bx,
                                                 const float* __restrict__ bh) {
    extern __shared__ float sm[];
    float* x_s = sm;               // [256][65] padded transpose
    float* Ws  = sm + 256 * 65;    // [32][256]
    const int tid = threadIdx.x;
    const int t   = blockIdx.y;
    const int n0  = blockIdx.x * 32;

    const float* xt = x + (size_t)t * BATCH * ISZ;
    #pragma unroll 4
    for (int r = 0; r < 64; r++) {
        int idx = r * 256 + tid;
        int b = idx >> 8;
        int i = idx & 255;
        x_s[i * 65 + b] = xt[idx];
    }
    const float* Wrow = Wx + (size_t)n0 * ISZ;
    #pragma unroll 4
    for (int r = 0; r < 32; r++) {
        int idx = r * 256 + tid;
        Ws[idx] = Wrow[idx];
    }
    __syncthreads();

    const int b  = tid & 63;
    const int ng = tid >> 6;
    float2 acc2[8];
    #pragma unroll
    for (int j = 0; j < 8; j++) acc2[j] = make_float2(0.f, 0.f);

    const float4* Ws4 = (const float4*)(Ws + (ng * 8) * ISZ);
    #pragma unroll 2
    for (int k4 = 0; k4 < 64; k4++) {
        const int k = k4 * 4;
        const float xa = x_s[(k + 0) * 65 + b];
        const float xb = x_s[(k + 1) * 65 + b];
        const float xc = x_s[(k + 2) * 65 + b];
        const float xd = x_s[(k + 3) * 65 + b];
        const float2 x01 = make_float2(xa, xb);
        const float2 x23 = make_float2(xc, xd);
        #pragma unroll
        for (int j = 0; j < 8; j++) {
            float4 w = Ws4[j * 64 + k4];
            acc2[j] = ffma2(make_float2(w.x, w.y), x01, acc2[j]);
            acc2[j] = ffma2(make_float2(w.z, w.w), x23, acc2[j]);
        }
    }

    const size_t base = ((size_t)t * GH + n0 + ng * 8) * BATCH + b;
    #pragma unroll
    for (int j = 0; j < 8; j++) {
        const int n = n0 + ng * 8 + j;
        g_gx[base + (size_t)j * BATCH] =
            acc2[j].x + acc2[j].y + __ldg(&bx[n]) + __ldg(&bh[n]);
    }
}

// ---------------- persistent recurrence kernel (R15, byte-identical) ----------------
// 128 CTAs (1/SM) x 512 threads (16 warps). CTA owns 4 hidden units (16 rows).
// h-quarter q produced by CTA group q (bid in [32q, 32q+32)) -> g_epochs[q].
// h transported as fp16 ([h][b] half); math fp32; outputs fp32 from registers.
// SMEM (float offsets): Wsp [0,8192), hs fp16 [8192,24576), red [24576,32768).
// Warp w: ke = w>>1 (k-eighth, 64 k), hlh = w&1 (hl pair). Lane = batch pair.
// Stager warps 0/5/10/15 stage quarter w/5 via cp.async.bulk.
// red race guarded by named barrier 2 (epi arrives after consuming red).
__global__ __launch_bounds__(512, 1) void lstm_persistent(
        const float* __restrict__ Wh,
        float* __restrict__ h_seq,
        float* __restrict__ out_hlast,
        float* __restrict__ out_clast) {
    extern __shared__ float sm[];
    float*  Wsp  = sm;                        // [512 k][16 r(hl,g)]  32 KB
    __half* hs   = (__half*)(sm + 8192);      // [512 k][64 b] fp16   64 KB
    float2* red  = (float2*)(sm + 24576);     // [8 ke][4 hl][2 gp][64 b] 32 KB
    unsigned long long* mbar = (unsigned long long*)(sm + 32768);

    const int tid  = threadIdx.x;
    const int lane = tid & 31;
    const int warp = tid >> 5;
    const int bp   = lane;
    const int hlh  = warp & 1;
    const int ke   = warp >> 1;              // k-eighth 0..7
    const int khq  = ke >> 1;                // k-quarter 0..3 (mbar index)
    const int bid  = blockIdx.x;
    const int h0   = bid * 4;
    const int gid  = bid >> 5;               // this CTA's producer group
    const bool is_stager = ((warp % 5) == 0);    // warps 0,5,10,15
    const int  sq = warp / 5;                    // staged quarter

    // ---- stage Wsp once: Wsp[k*16 + hl*4 + g] = Wh[g*512 + h0 + hl][k]
    #pragma unroll
    for (int it = 0; it < 16; it++) {
        int idx = it * 512 + tid;            // 0..8191 = r*512 + k
        int r = idx >> 9, k = idx & 511;
        int hl = r >> 2, g = r & 3;
        Wsp[k * 16 + hl * 4 + g] = Wh[((size_t)(g * HID + h0 + hl)) * HID + k];
    }
    if (tid == 0) {
        #pragma unroll
        for (int q = 0; q < 4; q++) mbar_init(smem_u32(&mbar[q]), 1);
    }

    // epilogue threads: tid < 128 -> cell (ehl = tid>>5, ebp = tid&31)
    const bool epi = (tid < 128);
    const int ehl = tid >> 5;
    const int ebp = tid & 31;
    const int eh  = h0 + ehl;
    float c0 = 0.0f, c1 = 0.0f;

    const unsigned my_bar  = smem_u32(&mbar[khq]);
    const unsigned hs_dst0 = smem_u32(hs);

    __syncthreads();

    int cur = 0;
    for (int t = 0; t < T_LEN; t++) {
        // ---- gx prefetch (h-independent; overlaps the epoch wait)
        float2 gxf, gxi, gxo, gxc;
        if (epi) {
            const float* gp = g_gx + ((size_t)t * GH + eh) * BATCH + 2 * ebp;
            gxf = __ldg((const float2*)(gp + (size_t)0 * HID * BATCH));
            gxi = __ldg((const float2*)(gp + (size_t)1 * HID * BATCH));
            gxo = __ldg((const float2*)(gp + (size_t)2 * HID * BATCH));
            gxc = __ldg((const float2*)(gp + (size_t)3 * HID * BATCH));
        }

        // ---- per-quarter stager: wait for its producer group, then copy 16 KB
        if (is_stager && lane == 0) {
            if (t > 0) {
                while (g_epochs[sq] < (unsigned)t) { __nanosleep(32); }
            }
            mbar_expect_tx(smem_u32(&mbar[sq]), 16384u);
            bulk_g2s(hs_dst0 + (unsigned)sq * 16384u,
                     (const char*)g_h[cur] + (unsigned)sq * 16384u,
                     16384u, smem_u32(&mbar[sq]));
        }

        // ---- wait only for this warp's k-quarter
        mbar_wait(my_bar, (unsigned)(t & 1));

        // ---- compute: 64 k x (2 hl rows x 2 gate-pairs x 2 batches)
        float2 A000 = make_float2(0.f, 0.f), A001 = A000, A010 = A000, A011 = A000;
        float2 A100 = A000, A101 = A000, A110 = A000, A111 = A000;

        const float*  wP = Wsp + (ke * 64) * 16 + 8 * hlh;
        const __half* hP = hs + (ke * 64) * 64 + 2 * bp;

        #pragma unroll 8
        for (int kl = 0; kl < 64; kl++) {
            const float4 w4a = *(const float4*)(wP);       // rows: hl=2hlh, gates 0..3
            const float4 w4b = *(const float4*)(wP + 4);   // rows: hl=2hlh+1
            const __half2 hh = *(const __half2*)(hP);
            const float2 hf  = __half22float2(hh);
            const float2 d0 = make_float2(hf.x, hf.x);
            const float2 d1 = make_float2(hf.y, hf.y);
            const float2 w01a = make_float2(w4a.x, w4a.y);
            const float2 w23a = make_float2(w4a.z, w4a.w);
            const float2 w01b = make_float2(w4b.x, w4b.y);
            const float2 w23b = make_float2(w4b.z, w4b.w);
            A000 = ffma2(w01a, d0, A000);
            A001 = ffma2(w01a, d1, A001);
            A010 = ffma2(w23a, d0, A010);
            A011 = ffma2(w23a, d1, A011);
            A100 = ffma2(w01b, d0, A100);
            A101 = ffma2(w01b, d1, A101);
            A110 = ffma2(w23b, d0, A110);
            A111 = ffma2(w23b, d1, A111);
            wP += 16;
            hP += 64;
        }

        // ---- guard: previous step's red consumers must be done (skip at t=0)
        if (t > 0 && !epi) {
            asm volatile("bar.sync 2, 512;" ::: "memory");
        }

        // ---- scatter partials: red[((ke*4+hl)*2+gp)*64 + b] (f2 = gate pair)
        {
            const int hlA = 2 * hlh, hlB = 2 * hlh + 1;
            float4* r0 = (float4*)(red + ((ke * 4 + hlA) * 2 + 0) * 64 + 2 * bp);
            float4* r1 = (float4*)(red + ((ke * 4 + hlA) * 2 + 1) * 64 + 2 * bp);
            float4* r2 = (float4*)(red + ((ke * 4 + hlB) * 2 + 0) * 64 + 2 * bp);
            float4* r3 = (float4*)(red + ((ke * 4 + hlB) * 2 + 1) * 64 + 2 * bp);
            *r0 = make_float4(A000.x, A000.y, A001.x, A001.y);
            *r1 = make_float4(A010.x, A010.y, A011.x, A011.y);
            *r2 = make_float4(A100.x, A100.y, A101.x, A101.y);
            *r3 = make_float4(A110.x, A110.y, A111.x, A111.y);
        }
        __syncthreads();

        // ---- reduce 8 k-eighths + gates + publish (epi threads only)
        if (epi) {
            float2 s01_0 = make_float2(0.f, 0.f), s01_1 = s01_0;
            float2 s23_0 = s01_0, s23_1 = s01_0;
            #pragma unroll
            for (int q = 0; q < 8; q++) {
                const float4 v01 = *(const float4*)(red + ((q * 4 + ehl) * 2 + 0) * 64 + 2 * ebp);
                const float4 v23 = *(const float4*)(red + ((q * 4 + ehl) * 2 + 1) * 64 + 2 * ebp);
                s01_0 = fadd2(s01_0, make_float2(v01.x, v01.y));
                s01_1 = fadd2(s01_1, make_float2(v01.z, v01.w));
                s23_0 = fadd2(s23_0, make_float2(v23.x, v23.y));
                s23_1 = fadd2(s23_1, make_float2(v23.z, v23.w));
            }
            // s01 = (f, i), s23 = (o, c); gx already contains bx + bh
            const float pf0 = s01_0.x + gxf.x, pf1 = s01_1.x + gxf.y;
            const float pi0 = s01_0.y + gxi.x, pi1 = s01_1.y + gxi.y;
            const float po0 = s23_0.x + gxo.x, po1 = s23_1.x + gxo.y;
            const float pc0 = s23_0.y + gxc.x, pc1 = s23_1.y + gxc.y;

            const float f0 = fast_sigmoid(pf0), f1 = fast_sigmoid(pf1);
            const float i0 = fast_sigmoid(pi0), i1 = fast_sigmoid(pi1);
            const float o0 = fast_sigmoid(po0), o1 = fast_sigmoid(po1);
            const float q0 = fast_tanh(pc0),    q1 = fast_tanh(pc1);

            c0 = f0 * c0 + i0 * q0;
            c1 = f1 * c1 + i1 * q1;
            const float hn0 = o0 * fast_tanh(c0);
            const float hn1 = o1 * fast_tanh(c1);

            // publish next-step h as fp16 (the only cross-CTA dependency)
            {
                __half2 h2 = __floats2half2_rn(hn0, hn1);
                __stcg((unsigned*)(g_h[cur ^ 1] + eh * BATCH + 2 * ebp),
                       *(unsigned*)&h2);
            }

            // red fully consumed (values folded into hn/c) -> release barrier 2
            asm volatile("bar.arrive 2, 512;" ::: "memory");

            // epi-only named barrier (warps 0-3, 128 threads), then release
            asm volatile("bar.sync 1, 128;" ::: "memory");
            if (tid == 0) {
                __threadfence();
                unsigned old = atomicAdd(&g_bars[gid], 1u);
                if (old == (unsigned)t * 32u + 31u) {
                    g_epochs[gid] = (unsigned)(t + 1);
                }
            }

            // off-critical-path outputs (full fp32 precision from registers)
            float* so = h_seq + ((size_t)t * BATCH + 2 * ebp) * HID + eh;
            so[0]   = hn0;
            so[HID] = hn1;
            if (t == T_LEN - 1) {
                out_hlast[(size_t)(2 * ebp) * HID + eh]     = hn0;
                out_hlast[(size_t)(2 * ebp + 1) * HID + eh] = hn1;
                out_clast[(size_t)(2 * ebp) * HID + eh]     = c0;
                out_clast[(size_t)(2 * ebp + 1) * HID + eh] = c1;
            }
        }

        cur ^= 1;
    }
}

// ---------------- launch ----------------
extern "C" void kernel_launch(void* const* d_in, const int* in_sizes, int n_in,
                              void* d_out, int out_size) {
    const float* x  = (const float*)d_in[0];
    const float* Wx = (const float*)d_in[1];
    const float* bx = (const float*)d_in[2];
    const float* Wh = (const float*)d_in[3];
    const float* bh = (const float*)d_in[4];

    float* out       = (float*)d_out;
    float* out_hlast = out + (size_t)T_LEN * BATCH * HID;
    float* out_clast = out_hlast + (size_t)BATCH * HID;

    const int gx_smem = (256 * 65 + 32 * 256) * sizeof(float);      // 99328 B
    const int ps_smem = (8192 + 16384 + 8192) * sizeof(float) + 64; // 131136 B
    cudaFuncSetAttribute(gx_kernel,       cudaFuncAttributeMaxDynamicSharedMemorySize, gx_smem);
    cudaFuncSetAttribute(lstm_persistent, cudaFuncAttributeMaxDynamicSharedMemorySize, ps_smem);

    init_state_kernel<<<128, 512>>>();
    gx_kernel<<<dim3(64, 512), 256, gx_smem>>>(x, Wx, bx, bh);
    lstm_persistent<<<NCTA, 512, ps_smem>>>(Wh, out, out_hlast, out_clast);
}